// round 12
// baseline (speedup 1.0000x reference)
#include <cuda_runtime.h>

#define EPS_F 1e-16f
#define NEG_SLOPE 0.2f

static const int MAXN = 50048;
static const int MAXE = 850048;
static const int NBMAX = 64;

// scratch (device globals — no allocation allowed)
__device__ int   g_deg[MAXN];          // zeroed at load; re-zeroed by scan_phase3
__device__ int   g_off[MAXN + 1];
__device__ int   g_cur[MAXN];
__device__ int   g_csr_src[MAXE];
__device__ int   g_csr_eid[MAXE];
__device__ float g_ew[MAXE];
__device__ int   g_bsum[NBMAX];
__device__ __align__(16) float g_h[(size_t)MAXN * 64];
__device__ __align__(16) float g_aggA[(size_t)MAXN * 64];
__device__ __align__(16) float g_aggB[(size_t)MAXN * 64];
__device__ float g_as[MAXN];
__device__ float g_ad[MAXN];

// ---------------------------------------------------------------------------
// Per-block edge-dtype detection: thread 0 inspects the first 64 odd 32-bit
// words (all-zero <=> little-endian int64 with values < 2^31). L2-hot.
// ---------------------------------------------------------------------------
__device__ __forceinline__ int detect_is64_block(const int* __restrict__ ei32,
                                                 int* s_flag) {
    if (threadIdx.x == 0) {
        int all_zero = 1;
        #pragma unroll
        for (int k = 0; k < 64; k++)
            if (ei32[2 * k + 1] != 0) { all_zero = 0; break; }
        *s_flag = all_zero;
    }
    __syncthreads();
    return *s_flag;
}

__device__ __forceinline__ void load_edge(const int* __restrict__ ei32, int is64,
                                          int e, int E, int n, int& s, int& d) {
    if (e < E) {
        if (is64) {
            const long long* ei = (const long long*)ei32;
            s = (int)ei[e]; d = (int)ei[E + e];
        } else {
            s = ei32[e]; d = ei32[E + e];
        }
    } else {
        s = d = e - E;   // self loop
    }
    s = min(max(s, 0), n - 1);
    d = min(max(d, 0), n - 1);
}

// Count per-dst degree; emit stacked (src,dst) as float at head of d_out.
__global__ void build_edges(const int* __restrict__ ei32, int E, int Ep, int n,
                            float* __restrict__ outIdx) {
    __shared__ int s_is64;
    int is64 = detect_is64_block(ei32, &s_is64);
    int e = blockIdx.x * blockDim.x + threadIdx.x;
    if (e >= Ep) return;
    int s, d;
    load_edge(ei32, is64, e, E, n, s, d);
    atomicAdd(&g_deg[d], 1);
    outIdx[e]      = (float)s;
    outIdx[Ep + e] = (float)d;
}

// ---------------------------------------------------------------------------
// Two-phase scan. phase1 = per-1024-chunk sums. phase3 = per-chunk scan;
// base computed by warp 0 with PARALLEL strided loads of the <=49 bsums.
// Also consume-and-resets g_deg for the next graph replay.
// ---------------------------------------------------------------------------
__global__ void scan_phase1(int n) {
    __shared__ int warpsum[32];
    int tid = threadIdx.x, lane = tid & 31, wid = tid >> 5;
    int i = blockIdx.x * 1024 + tid;
    int v = (i < n) ? g_deg[i] : 0;
    #pragma unroll
    for (int off = 16; off > 0; off >>= 1)
        v += __shfl_down_sync(0xffffffffu, v, off);
    if (lane == 0) warpsum[wid] = v;
    __syncthreads();
    if (wid == 0) {
        int t = warpsum[lane];
        #pragma unroll
        for (int off = 16; off > 0; off >>= 1)
            t += __shfl_down_sync(0xffffffffu, t, off);
        if (lane == 0) g_bsum[blockIdx.x] = t;
    }
}

__global__ void scan_phase3(int n) {
    __shared__ int warpsum[32];
    __shared__ int s_base;
    int tid = threadIdx.x, lane = tid & 31, wid = tid >> 5;
    if (wid == 0) {                      // parallel base: strided loads + reduce
        int b = 0;
        for (int j = lane; j < blockIdx.x; j += 32) b += g_bsum[j];
        #pragma unroll
        for (int off = 16; off > 0; off >>= 1)
            b += __shfl_down_sync(0xffffffffu, b, off);
        if (lane == 0) s_base = b;
    }
    int i = blockIdx.x * 1024 + tid;
    int v = (i < n) ? g_deg[i] : 0;
    if (i < n) g_deg[i] = 0;             // reset for next replay
    int incl = v;
    #pragma unroll
    for (int off = 1; off < 32; off <<= 1) {
        int t = __shfl_up_sync(0xffffffffu, incl, off);
        if (lane >= off) incl += t;
    }
    if (lane == 31) warpsum[wid] = incl;
    __syncthreads();
    if (wid == 0) {
        int ws = warpsum[lane];
        int wincl = ws;
        #pragma unroll
        for (int off = 1; off < 32; off <<= 1) {
            int t = __shfl_up_sync(0xffffffffu, wincl, off);
            if (lane >= off) wincl += t;
        }
        warpsum[lane] = wincl - ws;
    }
    __syncthreads();
    int excl = incl - v + warpsum[wid] + s_base;
    if (i < n) {
        g_off[i] = excl;
        g_cur[i] = excl;
        if (i == n - 1) g_off[n] = excl + v;
    }
}

__global__ void place_edges(const int* __restrict__ ei32, int E, int Ep, int n) {
    __shared__ int s_is64;
    int is64 = detect_is64_block(ei32, &s_is64);
    int e = blockIdx.x * blockDim.x + threadIdx.x;
    if (e >= Ep) return;
    int s, d;
    load_edge(ei32, is64, e, E, n, s, d);
    int pos = atomicAdd(&g_cur[d], 1);
    g_csr_src[pos] = s;
    g_csr_eid[pos] = e;
}

// ---------------------------------------------------------------------------
// GEMM: h = in @ W^T ; g_as = h.a_src ; g_ad = h.a_dst.
// 4 warps/block, 4 rows/warp, float4 smem loads (FMA-dense).
// INSEL: 0 = xin param, 1 = g_aggA, 2 = g_aggB.
// ---------------------------------------------------------------------------
template<int FIN, int FOUT, int INSEL>
__global__ __launch_bounds__(128)
void gat_gemm(const float* __restrict__ xin, const float* __restrict__ W,
              const float* __restrict__ av, const float* __restrict__ dv,
              int n) {
    constexpr int P = FIN + 4;
    __shared__ float sW[FOUT * P];
    __shared__ __align__(16) float srow[4][4][FIN];
    __shared__ float sA[FOUT];
    __shared__ float sD[FOUT];

    int tid = threadIdx.x;
    for (int i = tid; i < FOUT * FIN; i += 128) {
        int j = i / FIN, k = i % FIN;
        sW[j * P + k] = W[i];
    }
    if (tid < FOUT) { sA[tid] = av[tid]; sD[tid] = dv[tid]; }
    __syncthreads();

    const float* in = (INSEL == 0) ? xin : (INSEL == 1 ? g_aggA : g_aggB);
    int w = tid >> 5, lane = tid & 31;
    int j0 = lane, j1 = 32 + lane;

    for (int row0 = (blockIdx.x * 4 + w) * 4; row0 < n; row0 += gridDim.x * 16) {
        int nr = min(4, n - row0);
        for (int r = 0; r < nr; r++) {
            const float4* rp = (const float4*)(in + (size_t)(row0 + r) * FIN);
            if (FIN == 128) ((float4*)srow[w][r])[lane] = rp[lane];
            else if (lane < FIN / 4) ((float4*)srow[w][r])[lane] = rp[lane];
        }
        __syncwarp();

        float acc[4][FOUT / 32];
        #pragma unroll
        for (int r = 0; r < 4; r++)
            #pragma unroll
            for (int c = 0; c < FOUT / 32; c++) acc[r][c] = 0.f;

        #pragma unroll
        for (int kq = 0; kq < FIN / 4; kq++) {
            float4 w0 = *(const float4*)&sW[j0 * P + kq * 4];
            float4 w1;
            if (FOUT > 32) w1 = *(const float4*)&sW[j1 * P + kq * 4];
            #pragma unroll
            for (int r = 0; r < 4; r++) {
                float4 rv = ((const float4*)srow[w][r])[kq];
                acc[r][0] = fmaf(rv.x, w0.x, acc[r][0]);
                acc[r][0] = fmaf(rv.y, w0.y, acc[r][0]);
                acc[r][0] = fmaf(rv.z, w0.z, acc[r][0]);
                acc[r][0] = fmaf(rv.w, w0.w, acc[r][0]);
                if (FOUT > 32) {
                    acc[r][1] = fmaf(rv.x, w1.x, acc[r][1]);
                    acc[r][1] = fmaf(rv.y, w1.y, acc[r][1]);
                    acc[r][1] = fmaf(rv.z, w1.z, acc[r][1]);
                    acc[r][1] = fmaf(rv.w, w1.w, acc[r][1]);
                }
            }
        }

        for (int r = 0; r < nr; r++) {
            int row = row0 + r;
            float pa, pd;
            g_h[(size_t)row * FOUT + j0] = acc[r][0];
            pa = acc[r][0] * sA[j0];
            pd = acc[r][0] * sD[j0];
            if (FOUT > 32) {
                g_h[(size_t)row * FOUT + j1] = acc[r][1];
                pa = fmaf(acc[r][1], sA[j1], pa);
                pd = fmaf(acc[r][1], sD[j1], pd);
            }
            #pragma unroll
            for (int o = 16; o > 0; o >>= 1) {
                pa += __shfl_down_sync(0xffffffffu, pa, o);
                pd += __shfl_down_sync(0xffffffffu, pd, o);
            }
            if (lane == 0) { g_as[row] = pa; g_ad[row] = pd; }
        }
        __syncwarp();
    }
}

// ---------------------------------------------------------------------------
// CSR gather: warp per dst node, group-per-edge float4 layout.
// MODE 0 (layer1): out = relu(acc/s + b1) -> g_aggA, plus coalesced alpha.
// MODE 1 (layer2): out = relu(acc/s + b2) -> g_aggB.
// MODE 2 (layer3): out = acc/s + b3 -> outO.
// ---------------------------------------------------------------------------
template<int FOUT, int MODE>
__global__ __launch_bounds__(256)
void gat_gather(int n, const float* __restrict__ bias,
                float* __restrict__ outAlpha, float* __restrict__ outO) {
    constexpr int GSZ = FOUT / 4;      // lanes per group
    constexpr int NG  = 32 / GSZ;      // edges per iteration
    int wg = (blockIdx.x * blockDim.x + threadIdx.x) >> 5;
    int lane = threadIdx.x & 31;
    if (wg >= n) return;
    int d = wg;
    int beg = g_off[d], end = g_off[d + 1];
    float ad = g_ad[d];
    int g = lane / GSZ, fl = lane % GSZ;

    float4 acc = make_float4(0.f, 0.f, 0.f, 0.f);
    float s = 0.f;

    for (int p0 = beg; p0 < end; p0 += 32) {
        int cnt = min(32, end - p0);
        int src_l = 0;
        float w_l = 0.f;
        if (lane < cnt) {
            src_l = g_csr_src[p0 + lane];
            float v = g_as[src_l] + ad;
            v = v > 0.f ? v : NEG_SLOPE * v;
            w_l = __expf(v);
            if (MODE == 0) g_ew[p0 + lane] = w_l;
        }
        #pragma unroll 4
        for (int q = 0; q < cnt; q += NG) {
            int idx = q + g;
            float wh  = __shfl_sync(0xffffffffu, w_l, idx & 31);
            int  srch = __shfl_sync(0xffffffffu, src_l, idx & 31);
            float w2 = (idx < cnt) ? wh : 0.f;
            float4 hv = *(const float4*)&g_h[(size_t)srch * FOUT + fl * 4];
            acc.x = fmaf(w2, hv.x, acc.x);
            acc.y = fmaf(w2, hv.y, acc.y);
            acc.z = fmaf(w2, hv.z, acc.z);
            acc.w = fmaf(w2, hv.w, acc.w);
            s += w2;
        }
    }
    // combine groups
    #pragma unroll
    for (int off = GSZ; off < 32; off <<= 1) {
        s     += __shfl_xor_sync(0xffffffffu, s, off);
        acc.x += __shfl_xor_sync(0xffffffffu, acc.x, off);
        acc.y += __shfl_xor_sync(0xffffffffu, acc.y, off);
        acc.z += __shfl_xor_sync(0xffffffffu, acc.z, off);
        acc.w += __shfl_xor_sync(0xffffffffu, acc.w, off);
    }
    float sinv = 1.f / (s + EPS_F);

    if (lane < GSZ) {
        float4 b = *(const float4*)&bias[fl * 4];
        float4 o;
        if (MODE == 2) {
            o.x = fmaf(acc.x, sinv, b.x);
            o.y = fmaf(acc.y, sinv, b.y);
            o.z = fmaf(acc.z, sinv, b.z);
            o.w = fmaf(acc.w, sinv, b.w);
            *(float4*)&outO[(size_t)d * FOUT + fl * 4] = o;
        } else {
            o.x = fmaxf(fmaf(acc.x, sinv, b.x), 0.f);
            o.y = fmaxf(fmaf(acc.y, sinv, b.y), 0.f);
            o.z = fmaxf(fmaf(acc.z, sinv, b.z), 0.f);
            o.w = fmaxf(fmaf(acc.w, sinv, b.w), 0.f);
            float* outp = (MODE == 0) ? g_aggA : g_aggB;
            *(float4*)&outp[(size_t)d * FOUT + fl * 4] = o;
        }
    }

    if (MODE == 0) {
        for (int p = beg + lane; p < end; p += 32)
            outAlpha[g_csr_eid[p]] = g_ew[p] * sinv;
    }
}

// ---------------------------------------------------------------------------

extern "C" void kernel_launch(void* const* d_in, const int* in_sizes, int n_in,
                              void* d_out, int out_size) {
    const float* x    = (const float*)d_in[0];
    const int*   ei32 = (const int*)d_in[1];
    const float* W1 = (const float*)d_in[2];
    const float* a1s = (const float*)d_in[3];
    const float* a1d = (const float*)d_in[4];
    const float* b1 = (const float*)d_in[5];
    const float* W2 = (const float*)d_in[6];
    const float* a2s = (const float*)d_in[7];
    const float* a2d = (const float*)d_in[8];
    const float* b2 = (const float*)d_in[9];
    const float* W3 = (const float*)d_in[10];
    const float* a3s = (const float*)d_in[11];
    const float* a3d = (const float*)d_in[12];
    const float* b3 = (const float*)d_in[13];

    const int N  = in_sizes[0] / 128;     // 50000
    const int E  = in_sizes[1] / 2;       // 800000
    const int Ep = E + N;                 // with self loops

    float* out      = (float*)d_out;
    float* outAlpha = out + 2 * (size_t)Ep;
    float* outO     = out + 3 * (size_t)Ep;

    const int TB = 256;
    int ebl = (Ep + TB - 1) / TB;
    int nb = (N + 1023) / 1024;
    int gemm_grid = (N + 15) / 16;
    int gath_grid = (N + 7) / 8;

    // one-time side-stream for overlapping GEMM1 with preprocessing
    static cudaStream_t s2 = nullptr;
    static cudaEvent_t evFork = nullptr, evJoin = nullptr;
    if (!s2) {
        cudaStreamCreateWithFlags(&s2, cudaStreamNonBlocking);
        cudaEventCreateWithFlags(&evFork, cudaEventDisableTiming);
        cudaEventCreateWithFlags(&evJoin, cudaEventDisableTiming);
    }

    // fork: GEMM1 runs on s2, independent of edge preprocessing
    cudaEventRecord(evFork, 0);
    cudaStreamWaitEvent(s2, evFork, 0);
    gat_gemm<128, 64, 0><<<gemm_grid, 128, 0, s2>>>(x, W1, a1s, a1d, N);
    cudaEventRecord(evJoin, s2);

    // preprocessing chain on main stream
    build_edges<<<ebl, TB>>>(ei32, E, Ep, N, out);
    scan_phase1<<<nb, 1024>>>(N);
    scan_phase3<<<nb, 1024>>>(N);
    place_edges<<<ebl, TB>>>(ei32, E, Ep, N);

    // join: gather1 needs both CSR and GEMM1 results
    cudaStreamWaitEvent(0, evJoin, 0);

    // ---- layer 1: 128 -> 64 ----
    gat_gather<64, 0><<<gath_grid, TB>>>(N, b1, outAlpha, nullptr);

    // ---- layer 2: 64 -> 64 ----
    gat_gemm<64, 64, 1><<<gemm_grid, 128>>>(nullptr, W2, a2s, a2d, N);
    gat_gather<64, 1><<<gath_grid, TB>>>(N, b2, nullptr, nullptr);

    // ---- layer 3: 64 -> 32 ----
    gat_gemm<64, 32, 2><<<gemm_grid, 128>>>(nullptr, W3, a3s, a3d, N);
    gat_gather<32, 2><<<gath_grid, TB>>>(N, b3, nullptr, outO);
}

// round 13
// speedup vs baseline: 1.0301x; 1.0301x over previous
#include <cuda_runtime.h>
#include <cuda_fp16.h>

#define EPS_F 1e-16f
#define NEG_SLOPE 0.2f

static const int MAXN = 50048;
static const int MAXE = 850048;
static const int NBMAX = 64;

// scratch (device globals — no allocation allowed)
__device__ int    g_deg[MAXN];         // zeroed at load; re-zeroed by scan_phase3
__device__ int    g_off[MAXN + 1];
__device__ int    g_cur[MAXN];
__device__ int    g_csr_src[MAXE];
__device__ int    g_csr_eid[MAXE];
__device__ float  g_ew[MAXE];
__device__ int    g_bsum[NBMAX];
__device__ __align__(16) __half g_h16[(size_t)MAXN * 64];   // fp16 h (traffic halver)
__device__ __align__(16) float g_aggA[(size_t)MAXN * 64];
__device__ __align__(16) float g_aggB[(size_t)MAXN * 64];
__device__ float  g_as[MAXN];
__device__ float  g_ad[MAXN];

// ---------------------------------------------------------------------------
// Per-block edge-dtype detection (int64 vs int32), L2-hot.
// ---------------------------------------------------------------------------
__device__ __forceinline__ int detect_is64_block(const int* __restrict__ ei32,
                                                 int* s_flag) {
    if (threadIdx.x == 0) {
        int all_zero = 1;
        #pragma unroll
        for (int k = 0; k < 64; k++)
            if (ei32[2 * k + 1] != 0) { all_zero = 0; break; }
        *s_flag = all_zero;
    }
    __syncthreads();
    return *s_flag;
}

__device__ __forceinline__ void load_edge(const int* __restrict__ ei32, int is64,
                                          int e, int E, int n, int& s, int& d) {
    if (e < E) {
        if (is64) {
            const long long* ei = (const long long*)ei32;
            s = (int)ei[e]; d = (int)ei[E + e];
        } else {
            s = ei32[e]; d = ei32[E + e];
        }
    } else {
        s = d = e - E;   // self loop
    }
    s = min(max(s, 0), n - 1);
    d = min(max(d, 0), n - 1);
}

// Count per-dst degree; emit stacked (src,dst) as float at head of d_out.
__global__ void build_edges(const int* __restrict__ ei32, int E, int Ep, int n,
                            float* __restrict__ outIdx) {
    __shared__ int s_is64;
    int is64 = detect_is64_block(ei32, &s_is64);
    int e = blockIdx.x * blockDim.x + threadIdx.x;
    if (e >= Ep) return;
    int s, d;
    load_edge(ei32, is64, e, E, n, s, d);
    atomicAdd(&g_deg[d], 1);
    outIdx[e]      = (float)s;
    outIdx[Ep + e] = (float)d;
}

// ---------------------------------------------------------------------------
// Two-phase scan; phase3 base via parallel strided loads of <=49 bsums.
// Consume-and-resets g_deg for the next graph replay.
// ---------------------------------------------------------------------------
__global__ void scan_phase1(int n) {
    __shared__ int warpsum[32];
    int tid = threadIdx.x, lane = tid & 31, wid = tid >> 5;
    int i = blockIdx.x * 1024 + tid;
    int v = (i < n) ? g_deg[i] : 0;
    #pragma unroll
    for (int off = 16; off > 0; off >>= 1)
        v += __shfl_down_sync(0xffffffffu, v, off);
    if (lane == 0) warpsum[wid] = v;
    __syncthreads();
    if (wid == 0) {
        int t = warpsum[lane];
        #pragma unroll
        for (int off = 16; off > 0; off >>= 1)
            t += __shfl_down_sync(0xffffffffu, t, off);
        if (lane == 0) g_bsum[blockIdx.x] = t;
    }
}

__global__ void scan_phase3(int n) {
    __shared__ int warpsum[32];
    __shared__ int s_base;
    int tid = threadIdx.x, lane = tid & 31, wid = tid >> 5;
    if (wid == 0) {
        int b = 0;
        for (int j = lane; j < blockIdx.x; j += 32) b += g_bsum[j];
        #pragma unroll
        for (int off = 16; off > 0; off >>= 1)
            b += __shfl_down_sync(0xffffffffu, b, off);
        if (lane == 0) s_base = b;
    }
    int i = blockIdx.x * 1024 + tid;
    int v = (i < n) ? g_deg[i] : 0;
    if (i < n) g_deg[i] = 0;             // reset for next replay
    int incl = v;
    #pragma unroll
    for (int off = 1; off < 32; off <<= 1) {
        int t = __shfl_up_sync(0xffffffffu, incl, off);
        if (lane >= off) incl += t;
    }
    if (lane == 31) warpsum[wid] = incl;
    __syncthreads();
    if (wid == 0) {
        int ws = warpsum[lane];
        int wincl = ws;
        #pragma unroll
        for (int off = 1; off < 32; off <<= 1) {
            int t = __shfl_up_sync(0xffffffffu, wincl, off);
            if (lane >= off) wincl += t;
        }
        warpsum[lane] = wincl - ws;
    }
    __syncthreads();
    int excl = incl - v + warpsum[wid] + s_base;
    if (i < n) {
        g_off[i] = excl;
        g_cur[i] = excl;
        if (i == n - 1) g_off[n] = excl + v;
    }
}

__global__ void place_edges(const int* __restrict__ ei32, int E, int Ep, int n) {
    __shared__ int s_is64;
    int is64 = detect_is64_block(ei32, &s_is64);
    int e = blockIdx.x * blockDim.x + threadIdx.x;
    if (e >= Ep) return;
    int s, d;
    load_edge(ei32, is64, e, E, n, s, d);
    int pos = atomicAdd(&g_cur[d], 1);
    g_csr_src[pos] = s;
    g_csr_eid[pos] = e;
}

// ---------------------------------------------------------------------------
// GEMM: h(fp16) = in @ W^T ; g_as = h.a_src ; g_ad = h.a_dst (fp32 accums).
// 4 warps/block, 4 rows/warp, float4 smem loads (FMA-dense).
// INSEL: 0 = xin param, 1 = g_aggA, 2 = g_aggB.
// ---------------------------------------------------------------------------
template<int FIN, int FOUT, int INSEL>
__global__ __launch_bounds__(128)
void gat_gemm(const float* __restrict__ xin, const float* __restrict__ W,
              const float* __restrict__ av, const float* __restrict__ dv,
              int n) {
    constexpr int P = FIN + 4;
    __shared__ float sW[FOUT * P];
    __shared__ __align__(16) float srow[4][4][FIN];
    __shared__ float sA[FOUT];
    __shared__ float sD[FOUT];

    int tid = threadIdx.x;
    for (int i = tid; i < FOUT * FIN; i += 128) {
        int j = i / FIN, k = i % FIN;
        sW[j * P + k] = W[i];
    }
    if (tid < FOUT) { sA[tid] = av[tid]; sD[tid] = dv[tid]; }
    __syncthreads();

    const float* in = (INSEL == 0) ? xin : (INSEL == 1 ? g_aggA : g_aggB);
    int w = tid >> 5, lane = tid & 31;
    int j0 = lane, j1 = 32 + lane;

    for (int row0 = (blockIdx.x * 4 + w) * 4; row0 < n; row0 += gridDim.x * 16) {
        int nr = min(4, n - row0);
        for (int r = 0; r < nr; r++) {
            const float4* rp = (const float4*)(in + (size_t)(row0 + r) * FIN);
            if (FIN == 128) ((float4*)srow[w][r])[lane] = rp[lane];
            else if (lane < FIN / 4) ((float4*)srow[w][r])[lane] = rp[lane];
        }
        __syncwarp();

        float acc[4][FOUT / 32];
        #pragma unroll
        for (int r = 0; r < 4; r++)
            #pragma unroll
            for (int c = 0; c < FOUT / 32; c++) acc[r][c] = 0.f;

        #pragma unroll
        for (int kq = 0; kq < FIN / 4; kq++) {
            float4 w0 = *(const float4*)&sW[j0 * P + kq * 4];
            float4 w1;
            if (FOUT > 32) w1 = *(const float4*)&sW[j1 * P + kq * 4];
            #pragma unroll
            for (int r = 0; r < 4; r++) {
                float4 rv = ((const float4*)srow[w][r])[kq];
                acc[r][0] = fmaf(rv.x, w0.x, acc[r][0]);
                acc[r][0] = fmaf(rv.y, w0.y, acc[r][0]);
                acc[r][0] = fmaf(rv.z, w0.z, acc[r][0]);
                acc[r][0] = fmaf(rv.w, w0.w, acc[r][0]);
                if (FOUT > 32) {
                    acc[r][1] = fmaf(rv.x, w1.x, acc[r][1]);
                    acc[r][1] = fmaf(rv.y, w1.y, acc[r][1]);
                    acc[r][1] = fmaf(rv.z, w1.z, acc[r][1]);
                    acc[r][1] = fmaf(rv.w, w1.w, acc[r][1]);
                }
            }
        }

        for (int r = 0; r < nr; r++) {
            int row = row0 + r;
            float pa, pd;
            g_h16[(size_t)row * FOUT + j0] = __float2half_rn(acc[r][0]);
            pa = acc[r][0] * sA[j0];
            pd = acc[r][0] * sD[j0];
            if (FOUT > 32) {
                g_h16[(size_t)row * FOUT + j1] = __float2half_rn(acc[r][1]);
                pa = fmaf(acc[r][1], sA[j1], pa);
                pd = fmaf(acc[r][1], sD[j1], pd);
            }
            #pragma unroll
            for (int o = 16; o > 0; o >>= 1) {
                pa += __shfl_down_sync(0xffffffffu, pa, o);
                pd += __shfl_down_sync(0xffffffffu, pd, o);
            }
            if (lane == 0) { g_as[row] = pa; g_ad[row] = pd; }
        }
        __syncwarp();
    }
}

// ---------------------------------------------------------------------------
// CSR gather (fp16 h): warp per dst node. Each group of GSZ = FOUT/8 lanes
// handles one edge; lane loads uint4 = 8 halves; fp32 accumulate.
// MODE 0 (layer1): relu(acc/s + b1) -> g_aggA (fp32), plus coalesced alpha.
// MODE 1 (layer2): relu(acc/s + b2) -> g_aggB.
// MODE 2 (layer3): acc/s + b3 -> outO.
// ---------------------------------------------------------------------------
template<int FOUT, int MODE>
__global__ __launch_bounds__(256)
void gat_gather(int n, const float* __restrict__ bias,
                float* __restrict__ outAlpha, float* __restrict__ outO) {
    constexpr int GSZ = FOUT / 8;      // lanes per group (8 halves per lane)
    constexpr int NG  = 32 / GSZ;      // edges per iteration (4 or 8)
    int wg = (blockIdx.x * blockDim.x + threadIdx.x) >> 5;
    int lane = threadIdx.x & 31;
    if (wg >= n) return;
    int d = wg;
    int beg = g_off[d], end = g_off[d + 1];
    float ad = g_ad[d];
    int g = lane / GSZ, fl = lane % GSZ;

    float acc[8];
    #pragma unroll
    for (int j = 0; j < 8; j++) acc[j] = 0.f;
    float s = 0.f;

    for (int p0 = beg; p0 < end; p0 += 32) {
        int cnt = min(32, end - p0);
        int src_l = 0;
        float w_l = 0.f;
        if (lane < cnt) {
            src_l = g_csr_src[p0 + lane];
            float v = g_as[src_l] + ad;
            v = v > 0.f ? v : NEG_SLOPE * v;
            w_l = __expf(v);
            if (MODE == 0) g_ew[p0 + lane] = w_l;
        }
        #pragma unroll 2
        for (int q = 0; q < cnt; q += NG) {
            int idx = q + g;
            float wh  = __shfl_sync(0xffffffffu, w_l, idx & 31);
            int  srch = __shfl_sync(0xffffffffu, src_l, idx & 31);
            float w2 = (idx < cnt) ? wh : 0.f;
            uint4 hv = *(const uint4*)&g_h16[(size_t)srch * FOUT + fl * 8];
            const __half2* hp = (const __half2*)&hv;
            #pragma unroll
            for (int j = 0; j < 4; j++) {
                float2 f = __half22float2(hp[j]);
                acc[2 * j + 0] = fmaf(w2, f.x, acc[2 * j + 0]);
                acc[2 * j + 1] = fmaf(w2, f.y, acc[2 * j + 1]);
            }
            s += w2;
        }
    }
    // combine groups (butterfly across the NG groups)
    #pragma unroll
    for (int off = GSZ; off < 32; off <<= 1) {
        s += __shfl_xor_sync(0xffffffffu, s, off);
        #pragma unroll
        for (int j = 0; j < 8; j++)
            acc[j] += __shfl_xor_sync(0xffffffffu, acc[j], off);
    }
    float sinv = 1.f / (s + EPS_F);

    if (lane < GSZ) {
        float4 b0 = *(const float4*)&bias[fl * 8];
        float4 b1 = *(const float4*)&bias[fl * 8 + 4];
        float o[8];
        o[0] = fmaf(acc[0], sinv, b0.x); o[1] = fmaf(acc[1], sinv, b0.y);
        o[2] = fmaf(acc[2], sinv, b0.z); o[3] = fmaf(acc[3], sinv, b0.w);
        o[4] = fmaf(acc[4], sinv, b1.x); o[5] = fmaf(acc[5], sinv, b1.y);
        o[6] = fmaf(acc[6], sinv, b1.z); o[7] = fmaf(acc[7], sinv, b1.w);
        if (MODE == 2) {
            *(float4*)&outO[(size_t)d * FOUT + fl * 8]     = make_float4(o[0], o[1], o[2], o[3]);
            *(float4*)&outO[(size_t)d * FOUT + fl * 8 + 4] = make_float4(o[4], o[5], o[6], o[7]);
        } else {
            #pragma unroll
            for (int j = 0; j < 8; j++) o[j] = fmaxf(o[j], 0.f);
            float* outp = (MODE == 0) ? g_aggA : g_aggB;
            *(float4*)&outp[(size_t)d * FOUT + fl * 8]     = make_float4(o[0], o[1], o[2], o[3]);
            *(float4*)&outp[(size_t)d * FOUT + fl * 8 + 4] = make_float4(o[4], o[5], o[6], o[7]);
        }
    }

    if (MODE == 0) {
        for (int p = beg + lane; p < end; p += 32)
            outAlpha[g_csr_eid[p]] = g_ew[p] * sinv;
    }
}

// ---------------------------------------------------------------------------

extern "C" void kernel_launch(void* const* d_in, const int* in_sizes, int n_in,
                              void* d_out, int out_size) {
    const float* x    = (const float*)d_in[0];
    const int*   ei32 = (const int*)d_in[1];
    const float* W1 = (const float*)d_in[2];
    const float* a1s = (const float*)d_in[3];
    const float* a1d = (const float*)d_in[4];
    const float* b1 = (const float*)d_in[5];
    const float* W2 = (const float*)d_in[6];
    const float* a2s = (const float*)d_in[7];
    const float* a2d = (const float*)d_in[8];
    const float* b2 = (const float*)d_in[9];
    const float* W3 = (const float*)d_in[10];
    const float* a3s = (const float*)d_in[11];
    const float* a3d = (const float*)d_in[12];
    const float* b3 = (const float*)d_in[13];

    const int N  = in_sizes[0] / 128;     // 50000
    const int E  = in_sizes[1] / 2;       // 800000
    const int Ep = E + N;                 // with self loops

    float* out      = (float*)d_out;
    float* outAlpha = out + 2 * (size_t)Ep;
    float* outO     = out + 3 * (size_t)Ep;

    const int TB = 256;
    int ebl = (Ep + TB - 1) / TB;
    int nb = (N + 1023) / 1024;
    int gemm_grid = (N + 15) / 16;
    int gath_grid = (N + 7) / 8;

    // one-time side-stream for overlapping GEMM1 with preprocessing
    static cudaStream_t s2 = nullptr;
    static cudaEvent_t evFork = nullptr, evJoin = nullptr;
    if (!s2) {
        cudaStreamCreateWithFlags(&s2, cudaStreamNonBlocking);
        cudaEventCreateWithFlags(&evFork, cudaEventDisableTiming);
        cudaEventCreateWithFlags(&evJoin, cudaEventDisableTiming);
    }

    // fork: GEMM1 runs on s2, independent of edge preprocessing
    cudaEventRecord(evFork, 0);
    cudaStreamWaitEvent(s2, evFork, 0);
    gat_gemm<128, 64, 0><<<gemm_grid, 128, 0, s2>>>(x, W1, a1s, a1d, N);
    cudaEventRecord(evJoin, s2);

    // preprocessing chain on main stream
    build_edges<<<ebl, TB>>>(ei32, E, Ep, N, out);
    scan_phase1<<<nb, 1024>>>(N);
    scan_phase3<<<nb, 1024>>>(N);
    place_edges<<<ebl, TB>>>(ei32, E, Ep, N);

    // join: gather1 needs both CSR and GEMM1 results
    cudaStreamWaitEvent(0, evJoin, 0);

    // ---- layer 1: 128 -> 64 ----
    gat_gather<64, 0><<<gath_grid, TB>>>(N, b1, outAlpha, nullptr);

    // ---- layer 2: 64 -> 64 ----
    gat_gemm<64, 64, 1><<<gemm_grid, 128>>>(nullptr, W2, a2s, a2d, N);
    gat_gather<64, 1><<<gath_grid, TB>>>(N, b2, nullptr, nullptr);

    // ---- layer 3: 64 -> 32 ----
    gat_gemm<64, 32, 2><<<gemm_grid, 128>>>(nullptr, W3, a3s, a3d, N);
    gat_gather<32, 2><<<gath_grid, TB>>>(N, b3, nullptr, outO);
}

// round 14
// speedup vs baseline: 1.1143x; 1.0818x over previous
#include <cuda_runtime.h>
#include <cuda_fp16.h>

#define EPS_F 1e-16f
#define NEG_SLOPE 0.2f

static const int MAXN = 50048;
static const int MAXE = 850048;
static const int NBMAX = 64;
static const int GEMM_GRID = 592;      // grid-stride: W loaded 592x, not 3125x

// scratch (device globals — no allocation allowed)
__device__ int    g_deg[MAXN];         // zeroed at load; re-zeroed by scan_phase3
__device__ int    g_off[MAXN + 1];
__device__ int    g_cur[MAXN];
__device__ __align__(16) int2 g_edge[MAXE];    // packed (src,dst), clamped
__device__ int    g_csr_src[MAXE];
__device__ int    g_csr_eid[MAXE];
__device__ float  g_ew[MAXE];
__device__ int    g_bsum[NBMAX];
__device__ __align__(16) __half g_h16[(size_t)MAXN * 64];   // fp16 h
__device__ __align__(16) float g_aggA[(size_t)MAXN * 64];
__device__ __align__(16) float g_aggB[(size_t)MAXN * 64];
__device__ float  g_as[MAXN];
__device__ float  g_ad[MAXN];

// ---------------------------------------------------------------------------
// Per-block edge-dtype detection (int64 vs int32), L2-hot.
// ---------------------------------------------------------------------------
__device__ __forceinline__ int detect_is64_block(const int* __restrict__ ei32,
                                                 int* s_flag) {
    if (threadIdx.x == 0) {
        int all_zero = 1;
        #pragma unroll
        for (int k = 0; k < 64; k++)
            if (ei32[2 * k + 1] != 0) { all_zero = 0; break; }
        *s_flag = all_zero;
    }
    __syncthreads();
    return *s_flag;
}

// Decode + clamp + pack edges; count per-dst degree; emit stacked (src,dst)
// as float at head of d_out.
__global__ void build_edges(const int* __restrict__ ei32, int E, int Ep, int n,
                            float* __restrict__ outIdx) {
    __shared__ int s_is64;
    int is64 = detect_is64_block(ei32, &s_is64);
    int e = blockIdx.x * blockDim.x + threadIdx.x;
    if (e >= Ep) return;
    int s, d;
    if (e < E) {
        if (is64) {
            const long long* ei = (const long long*)ei32;
            s = (int)ei[e]; d = (int)ei[E + e];
        } else {
            s = ei32[e]; d = ei32[E + e];
        }
    } else {
        s = d = e - E;   // self loop
    }
    s = min(max(s, 0), n - 1);
    d = min(max(d, 0), n - 1);
    g_edge[e] = make_int2(s, d);
    atomicAdd(&g_deg[d], 1);
    outIdx[e]      = (float)s;
    outIdx[Ep + e] = (float)d;
}

// ---------------------------------------------------------------------------
// Two-phase scan; phase3 base via parallel strided loads of <=49 bsums.
// Consume-and-resets g_deg for the next graph replay.
// ---------------------------------------------------------------------------
__global__ void scan_phase1(int n) {
    __shared__ int warpsum[32];
    int tid = threadIdx.x, lane = tid & 31, wid = tid >> 5;
    int i = blockIdx.x * 1024 + tid;
    int v = (i < n) ? g_deg[i] : 0;
    #pragma unroll
    for (int off = 16; off > 0; off >>= 1)
        v += __shfl_down_sync(0xffffffffu, v, off);
    if (lane == 0) warpsum[wid] = v;
    __syncthreads();
    if (wid == 0) {
        int t = warpsum[lane];
        #pragma unroll
        for (int off = 16; off > 0; off >>= 1)
            t += __shfl_down_sync(0xffffffffu, t, off);
        if (lane == 0) g_bsum[blockIdx.x] = t;
    }
}

__global__ void scan_phase3(int n) {
    __shared__ int warpsum[32];
    __shared__ int s_base;
    int tid = threadIdx.x, lane = tid & 31, wid = tid >> 5;
    if (wid == 0) {
        int b = 0;
        for (int j = lane; j < blockIdx.x; j += 32) b += g_bsum[j];
        #pragma unroll
        for (int off = 16; off > 0; off >>= 1)
            b += __shfl_down_sync(0xffffffffu, b, off);
        if (lane == 0) s_base = b;
    }
    int i = blockIdx.x * 1024 + tid;
    int v = (i < n) ? g_deg[i] : 0;
    if (i < n) g_deg[i] = 0;             // reset for next replay
    int incl = v;
    #pragma unroll
    for (int off = 1; off < 32; off <<= 1) {
        int t = __shfl_up_sync(0xffffffffu, incl, off);
        if (lane >= off) incl += t;
    }
    if (lane == 31) warpsum[wid] = incl;
    __syncthreads();
    if (wid == 0) {
        int ws = warpsum[lane];
        int wincl = ws;
        #pragma unroll
        for (int off = 1; off < 32; off <<= 1) {
            int t = __shfl_up_sync(0xffffffffu, wincl, off);
            if (lane >= off) wincl += t;
        }
        warpsum[lane] = wincl - ws;
    }
    __syncthreads();
    int excl = incl - v + warpsum[wid] + s_base;
    if (i < n) {
        g_off[i] = excl;
        g_cur[i] = excl;
        if (i == n - 1) g_off[n] = excl + v;
    }
}

// Place edges from the packed int2 array (no re-decode of raw input).
__global__ void place_edges(int Ep) {
    int e = blockIdx.x * blockDim.x + threadIdx.x;
    if (e >= Ep) return;
    int2 ed = g_edge[e];
    int pos = atomicAdd(&g_cur[ed.y], 1);
    g_csr_src[pos] = ed.x;
    g_csr_eid[pos] = e;
}

// ---------------------------------------------------------------------------
// GEMM: h(fp16) = in @ W^T ; g_as = h.a_src ; g_ad = h.a_dst (fp32 accums).
// 4 warps/block, 4 rows/warp, float4 smem loads (FMA-dense). Grid-stride
// with GEMM_GRID blocks so W is loaded into smem only 592 times.
// INSEL: 0 = xin param, 1 = g_aggA, 2 = g_aggB.
// ---------------------------------------------------------------------------
template<int FIN, int FOUT, int INSEL>
__global__ __launch_bounds__(128)
void gat_gemm(const float* __restrict__ xin, const float* __restrict__ W,
              const float* __restrict__ av, const float* __restrict__ dv,
              int n) {
    constexpr int P = FIN + 4;
    __shared__ float sW[FOUT * P];
    __shared__ __align__(16) float srow[4][4][FIN];
    __shared__ float sA[FOUT];
    __shared__ float sD[FOUT];

    int tid = threadIdx.x;
    for (int i = tid; i < FOUT * FIN; i += 128) {
        int j = i / FIN, k = i % FIN;
        sW[j * P + k] = W[i];
    }
    if (tid < FOUT) { sA[tid] = av[tid]; sD[tid] = dv[tid]; }
    __syncthreads();

    const float* in = (INSEL == 0) ? xin : (INSEL == 1 ? g_aggA : g_aggB);
    int w = tid >> 5, lane = tid & 31;
    int j0 = lane, j1 = 32 + lane;

    for (int row0 = (blockIdx.x * 4 + w) * 4; row0 < n; row0 += gridDim.x * 16) {
        int nr = min(4, n - row0);
        for (int r = 0; r < nr; r++) {
            const float4* rp = (const float4*)(in + (size_t)(row0 + r) * FIN);
            if (FIN == 128) ((float4*)srow[w][r])[lane] = rp[lane];
            else if (lane < FIN / 4) ((float4*)srow[w][r])[lane] = rp[lane];
        }
        __syncwarp();

        float acc[4][FOUT / 32];
        #pragma unroll
        for (int r = 0; r < 4; r++)
            #pragma unroll
            for (int c = 0; c < FOUT / 32; c++) acc[r][c] = 0.f;

        #pragma unroll
        for (int kq = 0; kq < FIN / 4; kq++) {
            float4 w0 = *(const float4*)&sW[j0 * P + kq * 4];
            float4 w1;
            if (FOUT > 32) w1 = *(const float4*)&sW[j1 * P + kq * 4];
            #pragma unroll
            for (int r = 0; r < 4; r++) {
                float4 rv = ((const float4*)srow[w][r])[kq];
                acc[r][0] = fmaf(rv.x, w0.x, acc[r][0]);
                acc[r][0] = fmaf(rv.y, w0.y, acc[r][0]);
                acc[r][0] = fmaf(rv.z, w0.z, acc[r][0]);
                acc[r][0] = fmaf(rv.w, w0.w, acc[r][0]);
                if (FOUT > 32) {
                    acc[r][1] = fmaf(rv.x, w1.x, acc[r][1]);
                    acc[r][1] = fmaf(rv.y, w1.y, acc[r][1]);
                    acc[r][1] = fmaf(rv.z, w1.z, acc[r][1]);
                    acc[r][1] = fmaf(rv.w, w1.w, acc[r][1]);
                }
            }
        }

        for (int r = 0; r < nr; r++) {
            int row = row0 + r;
            float pa, pd;
            g_h16[(size_t)row * FOUT + j0] = __float2half_rn(acc[r][0]);
            pa = acc[r][0] * sA[j0];
            pd = acc[r][0] * sD[j0];
            if (FOUT > 32) {
                g_h16[(size_t)row * FOUT + j1] = __float2half_rn(acc[r][1]);
                pa = fmaf(acc[r][1], sA[j1], pa);
                pd = fmaf(acc[r][1], sD[j1], pd);
            }
            #pragma unroll
            for (int o = 16; o > 0; o >>= 1) {
                pa += __shfl_down_sync(0xffffffffu, pa, o);
                pd += __shfl_down_sync(0xffffffffu, pd, o);
            }
            if (lane == 0) { g_as[row] = pa; g_ad[row] = pd; }
        }
        __syncwarp();
    }
}

// ---------------------------------------------------------------------------
// CSR gather (fp16 h): warp per dst node. Group of GSZ = FOUT/8 lanes per
// edge; lane loads uint4 = 8 halves; fp32 accumulate.
// MODE 0: relu(acc/s + b1) -> g_aggA; alpha out (register fast path for
//         single-batch nodes, g_ew fallback for deg > 32).
// MODE 1: relu(acc/s + b2) -> g_aggB.
// MODE 2: acc/s + b3 -> outO.
// ---------------------------------------------------------------------------
template<int FOUT, int MODE>
__global__ __launch_bounds__(256)
void gat_gather(int n, const float* __restrict__ bias,
                float* __restrict__ outAlpha, float* __restrict__ outO) {
    constexpr int GSZ = FOUT / 8;      // lanes per group (8 halves per lane)
    constexpr int NG  = 32 / GSZ;      // edges per iteration (4 or 8)
    int wg = (blockIdx.x * blockDim.x + threadIdx.x) >> 5;
    int lane = threadIdx.x & 31;
    if (wg >= n) return;
    int d = wg;
    int beg = g_off[d], end = g_off[d + 1];
    float ad = g_ad[d];
    int g = lane / GSZ, fl = lane % GSZ;
    bool multi = (end - beg) > 32;     // more than one batch?

    float acc[8];
    #pragma unroll
    for (int j = 0; j < 8; j++) acc[j] = 0.f;
    float s = 0.f;
    float w_keep = 0.f;                // MODE 0 fast path registers
    int   eid_keep = 0;

    for (int p0 = beg; p0 < end; p0 += 32) {
        int cnt = min(32, end - p0);
        int src_l = 0;
        float w_l = 0.f;
        if (lane < cnt) {
            src_l = g_csr_src[p0 + lane];
            float v = g_as[src_l] + ad;
            v = v > 0.f ? v : NEG_SLOPE * v;
            w_l = __expf(v);
            if (MODE == 0) {
                if (multi) g_ew[p0 + lane] = w_l;
                else { w_keep = w_l; eid_keep = g_csr_eid[p0 + lane]; }
            }
        }
        #pragma unroll 2
        for (int q = 0; q < cnt; q += NG) {
            int idx = q + g;
            float wh  = __shfl_sync(0xffffffffu, w_l, idx & 31);
            int  srch = __shfl_sync(0xffffffffu, src_l, idx & 31);
            float w2 = (idx < cnt) ? wh : 0.f;
            uint4 hv = *(const uint4*)&g_h16[(size_t)srch * FOUT + fl * 8];
            const __half2* hp = (const __half2*)&hv;
            #pragma unroll
            for (int j = 0; j < 4; j++) {
                float2 f = __half22float2(hp[j]);
                acc[2 * j + 0] = fmaf(w2, f.x, acc[2 * j + 0]);
                acc[2 * j + 1] = fmaf(w2, f.y, acc[2 * j + 1]);
            }
            s += w2;
        }
    }
    // combine groups (butterfly across the NG groups)
    #pragma unroll
    for (int off = GSZ; off < 32; off <<= 1) {
        s += __shfl_xor_sync(0xffffffffu, s, off);
        #pragma unroll
        for (int j = 0; j < 8; j++)
            acc[j] += __shfl_xor_sync(0xffffffffu, acc[j], off);
    }
    float sinv = 1.f / (s + EPS_F);

    if (lane < GSZ) {
        float4 b0 = *(const float4*)&bias[fl * 8];
        float4 b1 = *(const float4*)&bias[fl * 8 + 4];
        float o[8];
        o[0] = fmaf(acc[0], sinv, b0.x); o[1] = fmaf(acc[1], sinv, b0.y);
        o[2] = fmaf(acc[2], sinv, b0.z); o[3] = fmaf(acc[3], sinv, b0.w);
        o[4] = fmaf(acc[4], sinv, b1.x); o[5] = fmaf(acc[5], sinv, b1.y);
        o[6] = fmaf(acc[6], sinv, b1.z); o[7] = fmaf(acc[7], sinv, b1.w);
        if (MODE == 2) {
            *(float4*)&outO[(size_t)d * FOUT + fl * 8]     = make_float4(o[0], o[1], o[2], o[3]);
            *(float4*)&outO[(size_t)d * FOUT + fl * 8 + 4] = make_float4(o[4], o[5], o[6], o[7]);
        } else {
            #pragma unroll
            for (int j = 0; j < 8; j++) o[j] = fmaxf(o[j], 0.f);
            float* outp = (MODE == 0) ? g_aggA : g_aggB;
            *(float4*)&outp[(size_t)d * FOUT + fl * 8]     = make_float4(o[0], o[1], o[2], o[3]);
            *(float4*)&outp[(size_t)d * FOUT + fl * 8 + 4] = make_float4(o[4], o[5], o[6], o[7]);
        }
    }

    if (MODE == 0) {
        if (!multi) {
            // single batch: everything still in registers
            if (beg + lane < end) outAlpha[eid_keep] = w_keep * sinv;
        } else {
            for (int p = beg + lane; p < end; p += 32)
                outAlpha[g_csr_eid[p]] = g_ew[p] * sinv;
        }
    }
}

// ---------------------------------------------------------------------------

extern "C" void kernel_launch(void* const* d_in, const int* in_sizes, int n_in,
                              void* d_out, int out_size) {
    const float* x    = (const float*)d_in[0];
    const int*   ei32 = (const int*)d_in[1];
    const float* W1 = (const float*)d_in[2];
    const float* a1s = (const float*)d_in[3];
    const float* a1d = (const float*)d_in[4];
    const float* b1 = (const float*)d_in[5];
    const float* W2 = (const float*)d_in[6];
    const float* a2s = (const float*)d_in[7];
    const float* a2d = (const float*)d_in[8];
    const float* b2 = (const float*)d_in[9];
    const float* W3 = (const float*)d_in[10];
    const float* a3s = (const float*)d_in[11];
    const float* a3d = (const float*)d_in[12];
    const float* b3 = (const float*)d_in[13];

    const int N  = in_sizes[0] / 128;     // 50000
    const int E  = in_sizes[1] / 2;       // 800000
    const int Ep = E + N;                 // with self loops

    float* out      = (float*)d_out;
    float* outAlpha = out + 2 * (size_t)Ep;
    float* outO     = out + 3 * (size_t)Ep;

    const int TB = 256;
    int ebl = (Ep + TB - 1) / TB;
    int nb = (N + 1023) / 1024;
    int gath_grid = (N + 7) / 8;

    // one-time side-stream for overlapping GEMM1 with preprocessing
    static cudaStream_t s2 = nullptr;
    static cudaEvent_t evFork = nullptr, evJoin = nullptr;
    if (!s2) {
        cudaStreamCreateWithFlags(&s2, cudaStreamNonBlocking);
        cudaEventCreateWithFlags(&evFork, cudaEventDisableTiming);
        cudaEventCreateWithFlags(&evJoin, cudaEventDisableTiming);
    }

    // fork: GEMM1 runs on s2, independent of edge preprocessing
    cudaEventRecord(evFork, 0);
    cudaStreamWaitEvent(s2, evFork, 0);
    gat_gemm<128, 64, 0><<<GEMM_GRID, 128, 0, s2>>>(x, W1, a1s, a1d, N);
    cudaEventRecord(evJoin, s2);

    // preprocessing chain on main stream
    build_edges<<<ebl, TB>>>(ei32, E, Ep, N, out);
    scan_phase1<<<nb, 1024>>>(N);
    scan_phase3<<<nb, 1024>>>(N);
    place_edges<<<ebl, TB>>>(Ep);

    // join: gather1 needs both CSR and GEMM1 results
    cudaStreamWaitEvent(0, evJoin, 0);

    // ---- layer 1: 128 -> 64 ----
    gat_gather<64, 0><<<gath_grid, TB>>>(N, b1, outAlpha, nullptr);

    // ---- layer 2: 64 -> 64 ----
    gat_gemm<64, 64, 1><<<GEMM_GRID, 128>>>(nullptr, W2, a2s, a2d, N);
    gat_gather<64, 1><<<gath_grid, TB>>>(N, b2, nullptr, nullptr);

    // ---- layer 3: 64 -> 32 ----
    gat_gemm<64, 32, 2><<<GEMM_GRID, 128>>>(nullptr, W3, a3s, a3d, N);
    gat_gather<32, 2><<<gath_grid, TB>>>(N, b3, nullptr, outO);
}

// round 15
// speedup vs baseline: 1.1233x; 1.0080x over previous
#include <cuda_runtime.h>
#include <cuda_fp16.h>

#define EPS_F 1e-16f
#define NEG_SLOPE 0.2f
#define LOG2E_F 1.4426950408889634f

static const int MAXN = 50048;
static const int MAXE = 850048;
static const int NBMAX = 256;
static const int GEMM_GRID = 592;      // grid-stride: W loaded 592x, not 3125x

// scratch (device globals — no allocation allowed)
__device__ int    g_deg[MAXN];         // zeroed at load; re-zeroed by scan_phase3
__device__ int    g_off[MAXN + 1];
__device__ int    g_cur[MAXN];
__device__ __align__(16) int2 g_edge[MAXE];    // packed (src,dst), clamped
__device__ int    g_csr_src[MAXE];
__device__ int    g_csr_eid[MAXE];
__device__ float  g_ew[MAXE];
__device__ int    g_bsum[NBMAX];
__device__ __align__(16) __half g_h16[(size_t)MAXN * 64];   // fp16 h
__device__ __align__(16) float g_aggA[(size_t)MAXN * 64];
__device__ __align__(16) float g_aggB[(size_t)MAXN * 64];
__device__ float  g_as[MAXN];          // pre-scaled by log2(e)
__device__ float  g_ad[MAXN];          // pre-scaled by log2(e)

// ---------------------------------------------------------------------------
// Parallel per-block dtype detection: warp 0 lanes load 2 odd words each,
// one ballot. (int64 little-endian with values < 2^31 <=> all odd words 0.)
// ---------------------------------------------------------------------------
__device__ __forceinline__ int detect_is64_block(const int* __restrict__ ei32,
                                                 int* s_flag) {
    if (threadIdx.x < 32) {
        int v0 = ei32[2 * threadIdx.x + 1];
        int v1 = ei32[2 * (threadIdx.x + 32) + 1];
        unsigned nz = __ballot_sync(0xffffffffu, (v0 | v1) != 0);
        if (threadIdx.x == 0) *s_flag = (nz == 0);
    }
    __syncthreads();
    return *s_flag;
}

// Decode + clamp + pack edges; count per-dst degree; emit stacked (src,dst)
// as float at head of d_out.
__global__ void build_edges(const int* __restrict__ ei32, int E, int Ep, int n,
                            float* __restrict__ outIdx) {
    __shared__ int s_is64;
    int is64 = detect_is64_block(ei32, &s_is64);
    int e = blockIdx.x * blockDim.x + threadIdx.x;
    if (e >= Ep) return;
    int s, d;
    if (e < E) {
        if (is64) {
            const long long* ei = (const long long*)ei32;
            s = (int)ei[e]; d = (int)ei[E + e];
        } else {
            s = ei32[e]; d = ei32[E + e];
        }
    } else {
        s = d = e - E;   // self loop
    }
    s = min(max(s, 0), n - 1);
    d = min(max(d, 0), n - 1);
    g_edge[e] = make_int2(s, d);
    atomicAdd(&g_deg[d], 1);
    outIdx[e]      = (float)s;
    outIdx[Ep + e] = (float)d;
}

// ---------------------------------------------------------------------------
// Two-phase scan, 256-thread chunks x 196 blocks (chip-wide latency hiding).
// phase3 base = parallel strided sum of preceding bsums; consume-and-resets
// g_deg for the next graph replay.
// ---------------------------------------------------------------------------
__global__ void scan_phase1(int n) {
    __shared__ int warpsum[8];
    int tid = threadIdx.x, lane = tid & 31, wid = tid >> 5;
    int i = blockIdx.x * 256 + tid;
    int v = (i < n) ? g_deg[i] : 0;
    #pragma unroll
    for (int off = 16; off > 0; off >>= 1)
        v += __shfl_down_sync(0xffffffffu, v, off);
    if (lane == 0) warpsum[wid] = v;
    __syncthreads();
    if (tid == 0) {
        int t = 0;
        #pragma unroll
        for (int j = 0; j < 8; j++) t += warpsum[j];
        g_bsum[blockIdx.x] = t;
    }
}

__global__ void scan_phase3(int n) {
    __shared__ int warpsum[8];
    __shared__ int s_base;
    int tid = threadIdx.x, lane = tid & 31, wid = tid >> 5;
    if (wid == 0) {                      // parallel base over <=195 bsums
        int b = 0;
        for (int j = lane; j < blockIdx.x; j += 32) b += g_bsum[j];
        #pragma unroll
        for (int off = 16; off > 0; off >>= 1)
            b += __shfl_down_sync(0xffffffffu, b, off);
        if (lane == 0) s_base = b;
    }
    int i = blockIdx.x * 256 + tid;
    int v = (i < n) ? g_deg[i] : 0;
    if (i < n) g_deg[i] = 0;             // reset for next replay
    int incl = v;
    #pragma unroll
    for (int off = 1; off < 32; off <<= 1) {
        int t = __shfl_up_sync(0xffffffffu, incl, off);
        if (lane >= off) incl += t;
    }
    if (lane == 31) warpsum[wid] = incl;
    __syncthreads();
    if (tid < 8) {
        int ws = warpsum[tid];
        int wincl = ws;
        #pragma unroll
        for (int off = 1; off < 8; off <<= 1) {
            int t = __shfl_up_sync(0xffu, wincl, off);
            if (tid >= off) wincl += t;
        }
        warpsum[tid] = wincl - ws;
    }
    __syncthreads();
    int excl = incl - v + warpsum[wid] + s_base;
    if (i < n) {
        g_off[i] = excl;
        g_cur[i] = excl;
        if (i == n - 1) g_off[n] = excl + v;
    }
}

// Place edges from the packed int2 array (no re-decode of raw input).
__global__ void place_edges(int Ep) {
    int e = blockIdx.x * blockDim.x + threadIdx.x;
    if (e >= Ep) return;
    int2 ed = g_edge[e];
    int pos = atomicAdd(&g_cur[ed.y], 1);
    g_csr_src[pos] = ed.x;
    g_csr_eid[pos] = e;
}

// ---------------------------------------------------------------------------
// GEMM: h(fp16) = in @ W^T ; g_as = log2e * h.a_src ; g_ad = log2e * h.a_dst.
// 4 warps/block, 4 rows/warp, float4 smem loads (FMA-dense). Grid-stride.
// INSEL: 0 = xin param, 1 = g_aggA, 2 = g_aggB.
// ---------------------------------------------------------------------------
template<int FIN, int FOUT, int INSEL>
__global__ __launch_bounds__(128)
void gat_gemm(const float* __restrict__ xin, const float* __restrict__ W,
              const float* __restrict__ av, const float* __restrict__ dv,
              int n) {
    constexpr int P = FIN + 4;
    __shared__ float sW[FOUT * P];
    __shared__ __align__(16) float srow[4][4][FIN];
    __shared__ float sA[FOUT];
    __shared__ float sD[FOUT];

    int tid = threadIdx.x;
    for (int i = tid; i < FOUT * FIN; i += 128) {
        int j = i / FIN, k = i % FIN;
        sW[j * P + k] = W[i];
    }
    if (tid < FOUT) { sA[tid] = av[tid]; sD[tid] = dv[tid]; }
    __syncthreads();

    const float* in = (INSEL == 0) ? xin : (INSEL == 1 ? g_aggA : g_aggB);
    int w = tid >> 5, lane = tid & 31;
    int j0 = lane, j1 = 32 + lane;

    for (int row0 = (blockIdx.x * 4 + w) * 4; row0 < n; row0 += gridDim.x * 16) {
        int nr = min(4, n - row0);
        for (int r = 0; r < nr; r++) {
            const float4* rp = (const float4*)(in + (size_t)(row0 + r) * FIN);
            if (FIN == 128) ((float4*)srow[w][r])[lane] = rp[lane];
            else if (lane < FIN / 4) ((float4*)srow[w][r])[lane] = rp[lane];
        }
        __syncwarp();

        float acc[4][FOUT / 32];
        #pragma unroll
        for (int r = 0; r < 4; r++)
            #pragma unroll
            for (int c = 0; c < FOUT / 32; c++) acc[r][c] = 0.f;

        #pragma unroll
        for (int kq = 0; kq < FIN / 4; kq++) {
            float4 w0 = *(const float4*)&sW[j0 * P + kq * 4];
            float4 w1;
            if (FOUT > 32) w1 = *(const float4*)&sW[j1 * P + kq * 4];
            #pragma unroll
            for (int r = 0; r < 4; r++) {
                float4 rv = ((const float4*)srow[w][r])[kq];
                acc[r][0] = fmaf(rv.x, w0.x, acc[r][0]);
                acc[r][0] = fmaf(rv.y, w0.y, acc[r][0]);
                acc[r][0] = fmaf(rv.z, w0.z, acc[r][0]);
                acc[r][0] = fmaf(rv.w, w0.w, acc[r][0]);
                if (FOUT > 32) {
                    acc[r][1] = fmaf(rv.x, w1.x, acc[r][1]);
                    acc[r][1] = fmaf(rv.y, w1.y, acc[r][1]);
                    acc[r][1] = fmaf(rv.z, w1.z, acc[r][1]);
                    acc[r][1] = fmaf(rv.w, w1.w, acc[r][1]);
                }
            }
        }

        for (int r = 0; r < nr; r++) {
            int row = row0 + r;
            float pa, pd;
            g_h16[(size_t)row * FOUT + j0] = __float2half_rn(acc[r][0]);
            pa = acc[r][0] * sA[j0];
            pd = acc[r][0] * sD[j0];
            if (FOUT > 32) {
                g_h16[(size_t)row * FOUT + j1] = __float2half_rn(acc[r][1]);
                pa = fmaf(acc[r][1], sA[j1], pa);
                pd = fmaf(acc[r][1], sD[j1], pd);
            }
            #pragma unroll
            for (int o = 16; o > 0; o >>= 1) {
                pa += __shfl_down_sync(0xffffffffu, pa, o);
                pd += __shfl_down_sync(0xffffffffu, pd, o);
            }
            if (lane == 0) {
                g_as[row] = pa * LOG2E_F;   // exp2 folding
                g_ad[row] = pd * LOG2E_F;
            }
        }
        __syncwarp();
    }
}

// ---------------------------------------------------------------------------
// CSR gather (fp16 h): warp per dst node. Group of GSZ = FOUT/8 lanes per
// edge; lane loads uint4 = 8 halves; fp32 accumulate. Weights via exp2f
// (as/ad pre-scaled by log2e; leaky_relu is positively homogeneous).
// MODE 0: relu(acc/s + b1) -> g_aggA; alpha out (register fast path).
// MODE 1: relu(acc/s + b2) -> g_aggB.
// MODE 2: acc/s + b3 -> outO.
// ---------------------------------------------------------------------------
template<int FOUT, int MODE>
__global__ __launch_bounds__(256)
void gat_gather(int n, const float* __restrict__ bias,
                float* __restrict__ outAlpha, float* __restrict__ outO) {
    constexpr int GSZ = FOUT / 8;      // lanes per group (8 halves per lane)
    constexpr int NG  = 32 / GSZ;      // edges per iteration (4 or 8)
    int wg = (blockIdx.x * blockDim.x + threadIdx.x) >> 5;
    int lane = threadIdx.x & 31;
    if (wg >= n) return;
    int d = wg;
    int beg = g_off[d], end = g_off[d + 1];
    float ad = g_ad[d];
    int g = lane / GSZ, fl = lane % GSZ;
    bool multi = (end - beg) > 32;     // more than one batch?

    float acc[8];
    #pragma unroll
    for (int j = 0; j < 8; j++) acc[j] = 0.f;
    float s = 0.f;
    float w_keep = 0.f;                // MODE 0 fast path registers
    int   eid_keep = 0;

    for (int p0 = beg; p0 < end; p0 += 32) {
        int cnt = min(32, end - p0);
        int src_l = 0;
        float w_l = 0.f;
        if (lane < cnt) {
            src_l = g_csr_src[p0 + lane];
            float v = g_as[src_l] + ad;
            v = v > 0.f ? v : NEG_SLOPE * v;
            w_l = exp2f(v);
            if (MODE == 0) {
                if (multi) g_ew[p0 + lane] = w_l;
                else { w_keep = w_l; eid_keep = g_csr_eid[p0 + lane]; }
            }
        }
        #pragma unroll 2
        for (int q = 0; q < cnt; q += NG) {
            int idx = q + g;
            float wh  = __shfl_sync(0xffffffffu, w_l, idx & 31);
            int  srch = __shfl_sync(0xffffffffu, src_l, idx & 31);
            float w2 = (idx < cnt) ? wh : 0.f;
            uint4 hv = *(const uint4*)&g_h16[(size_t)srch * FOUT + fl * 8];
            const __half2* hp = (const __half2*)&hv;
            #pragma unroll
            for (int j = 0; j < 4; j++) {
                float2 f = __half22float2(hp[j]);
                acc[2 * j + 0] = fmaf(w2, f.x, acc[2 * j + 0]);
                acc[2 * j + 1] = fmaf(w2, f.y, acc[2 * j + 1]);
            }
            s += w2;
        }
    }
    // combine groups (butterfly across the NG groups)
    #pragma unroll
    for (int off = GSZ; off < 32; off <<= 1) {
        s += __shfl_xor_sync(0xffffffffu, s, off);
        #pragma unroll
        for (int j = 0; j < 8; j++)
            acc[j] += __shfl_xor_sync(0xffffffffu, acc[j], off);
    }
    float sinv = __fdividef(1.f, s + EPS_F);

    if (lane < GSZ) {
        float4 b0 = *(const float4*)&bias[fl * 8];
        float4 b1 = *(const float4*)&bias[fl * 8 + 4];
        float o[8];
        o[0] = fmaf(acc[0], sinv, b0.x); o[1] = fmaf(acc[1], sinv, b0.y);
        o[2] = fmaf(acc[2], sinv, b0.z); o[3] = fmaf(acc[3], sinv, b0.w);
        o[4] = fmaf(acc[4], sinv, b1.x); o[5] = fmaf(acc[5], sinv, b1.y);
        o[6] = fmaf(acc[6], sinv, b1.z); o[7] = fmaf(acc[7], sinv, b1.w);
        if (MODE == 2) {
            *(float4*)&outO[(size_t)d * FOUT + fl * 8]     = make_float4(o[0], o[1], o[2], o[3]);
            *(float4*)&outO[(size_t)d * FOUT + fl * 8 + 4] = make_float4(o[4], o[5], o[6], o[7]);
        } else {
            #pragma unroll
            for (int j = 0; j < 8; j++) o[j] = fmaxf(o[j], 0.f);
            float* outp = (MODE == 0) ? g_aggA : g_aggB;
            *(float4*)&outp[(size_t)d * FOUT + fl * 8]     = make_float4(o[0], o[1], o[2], o[3]);
            *(float4*)&outp[(size_t)d * FOUT + fl * 8 + 4] = make_float4(o[4], o[5], o[6], o[7]);
        }
    }

    if (MODE == 0) {
        if (!multi) {
            if (beg + lane < end) outAlpha[eid_keep] = w_keep * sinv;
        } else {
            for (int p = beg + lane; p < end; p += 32)
                outAlpha[g_csr_eid[p]] = g_ew[p] * sinv;
        }
    }
}

// ---------------------------------------------------------------------------

extern "C" void kernel_launch(void* const* d_in, const int* in_sizes, int n_in,
                              void* d_out, int out_size) {
    const float* x    = (const float*)d_in[0];
    const int*   ei32 = (const int*)d_in[1];
    const float* W1 = (const float*)d_in[2];
    const float* a1s = (const float*)d_in[3];
    const float* a1d = (const float*)d_in[4];
    const float* b1 = (const float*)d_in[5];
    const float* W2 = (const float*)d_in[6];
    const float* a2s = (const float*)d_in[7];
    const float* a2d = (const float*)d_in[8];
    const float* b2 = (const float*)d_in[9];
    const float* W3 = (const float*)d_in[10];
    const float* a3s = (const float*)d_in[11];
    const float* a3d = (const float*)d_in[12];
    const float* b3 = (const float*)d_in[13];

    const int N  = in_sizes[0] / 128;     // 50000
    const int E  = in_sizes[1] / 2;       // 800000
    const int Ep = E + N;                 // with self loops

    float* out      = (float*)d_out;
    float* outAlpha = out + 2 * (size_t)Ep;
    float* outO     = out + 3 * (size_t)Ep;

    const int TB = 256;
    int ebl = (Ep + TB - 1) / TB;
    int nb = (N + 255) / 256;             // 196 scan blocks
    int gath_grid = (N + 7) / 8;

    // one-time side-stream for overlapping GEMM1 with preprocessing
    static cudaStream_t s2 = nullptr;
    static cudaEvent_t evFork = nullptr, evJoin = nullptr;
    if (!s2) {
        cudaStreamCreateWithFlags(&s2, cudaStreamNonBlocking);
        cudaEventCreateWithFlags(&evFork, cudaEventDisableTiming);
        cudaEventCreateWithFlags(&evJoin, cudaEventDisableTiming);
    }

    // fork: GEMM1 runs on s2, independent of edge preprocessing
    cudaEventRecord(evFork, 0);
    cudaStreamWaitEvent(s2, evFork, 0);
    gat_gemm<128, 64, 0><<<GEMM_GRID, 128, 0, s2>>>(x, W1, a1s, a1d, N);
    cudaEventRecord(evJoin, s2);

    // preprocessing chain on main stream
    build_edges<<<ebl, TB>>>(ei32, E, Ep, N, out);
    scan_phase1<<<nb, 256>>>(N);
    scan_phase3<<<nb, 256>>>(N);
    place_edges<<<ebl, TB>>>(Ep);

    // join: gather1 needs both CSR and GEMM1 results
    cudaStreamWaitEvent(0, evJoin, 0);

    // ---- layer 1: 128 -> 64 ----
    gat_gather<64, 0><<<gath_grid, TB>>>(N, b1, outAlpha, nullptr);

    // ---- layer 2: 64 -> 64 ----
    gat_gemm<64, 64, 1><<<GEMM_GRID, 128>>>(nullptr, W2, a2s, a2d, N);
    gat_gather<64, 1><<<gath_grid, TB>>>(N, b2, nullptr, nullptr);

    // ---- layer 3: 64 -> 32 ----
    gat_gemm<64, 32, 2><<<GEMM_GRID, 128>>>(nullptr, W3, a3s, a3d, N);
    gat_gather<32, 2><<<gath_grid, TB>>>(N, b3, nullptr, outO);
}